// round 1
// baseline (speedup 1.0000x reference)
#include <cuda_runtime.h>
#include <cuda_bf16.h>
#include <cstdint>

// out[b, o] = bias[o] + sum over UNIQUE (i0,i1) pairs in batch row b of
//             W[i0*350 + i1, o]
//
// Inputs (metadata order):
//   d_in[0]: x    int32  [32, 200, 3]   (b, i0, i1)
//   d_in[1]: W    float  [2150400, 5]
//   d_in[2]: b    float  [5]
// Output: float [32, 5]

#define NB     32
#define NHITS  200
#define D1     350
#define OUT    5
#define TPB    256   // 8 warps

__global__ void __launch_bounds__(TPB, 1)
prtnn_kernel(const int* __restrict__ x,
             const float* __restrict__ W,
             const float* __restrict__ bias,
             float* __restrict__ out)
{
    const int b = blockIdx.x;
    const int t = threadIdx.x;

    __shared__ int   feats[NHITS];
    __shared__ float warp_acc[TPB / 32][OUT];

    // 1) compute flattened feature index per hit
    if (t < NHITS) {
        const int* xp = x + ((size_t)b * NHITS + t) * 3;
        // xp[0] == b always; feature = i0*350 + i1
        feats[t] = xp[1] * D1 + xp[2];
    }
    __syncthreads();

    // 2) gather W row if this hit is the FIRST occurrence of its feature
    //    (dedup matches scatter .set(1.0) semantics)
    float acc[OUT] = {0.f, 0.f, 0.f, 0.f, 0.f};
    if (t < NHITS) {
        const int f = feats[t];
        bool uniq = true;
        for (int j = 0; j < t; ++j) {
            if (feats[j] == f) { uniq = false; break; }
        }
        if (uniq) {
            const float* w = W + (size_t)f * OUT;
            #pragma unroll
            for (int o = 0; o < OUT; ++o) acc[o] = __ldg(w + o);
        }
    }

    // 3) warp tree-reduce the 5 partial sums
    #pragma unroll
    for (int off = 16; off > 0; off >>= 1) {
        #pragma unroll
        for (int o = 0; o < OUT; ++o)
            acc[o] += __shfl_down_sync(0xFFFFFFFFu, acc[o], off);
    }
    const int wid  = t >> 5;
    const int lane = t & 31;
    if (lane == 0) {
        #pragma unroll
        for (int o = 0; o < OUT; ++o) warp_acc[wid][o] = acc[o];
    }
    __syncthreads();

    // 4) cross-warp reduce + bias + store (5 threads write 5 outputs)
    if (t < OUT) {
        float s = bias[t];
        #pragma unroll
        for (int w = 0; w < TPB / 32; ++w) s += warp_acc[w][t];
        out[(size_t)b * OUT + t] = s;
    }
}

extern "C" void kernel_launch(void* const* d_in, const int* in_sizes, int n_in,
                              void* d_out, int out_size)
{
    const int*   x    = (const int*)d_in[0];
    const float* W    = (const float*)d_in[1];
    const float* bias = (const float*)d_in[2];
    float*       out  = (float*)d_out;

    prtnn_kernel<<<NB, TPB>>>(x, W, bias, out);
}

// round 2
// speedup vs baseline: 1.4390x; 1.4390x over previous
#include <cuda_runtime.h>
#include <cuda_bf16.h>
#include <cstdint>

// out[b, o] = bias[o] + sum over UNIQUE (i0,i1) pairs in batch row b of
//             W[i0*350 + i1, o]
//
// Inputs (metadata order):
//   d_in[0]: x    int32  [32, 200, 3]   (b, i0, i1)
//   d_in[1]: W    float  [2150400, 5]
//   d_in[2]: b    float  [5]
// Output: float [32, 5]

#define NB      32
#define NHITS   200
#define D1      350
#define OUT     5
#define TPB     256            // 8 warps
#define HASH_SZ 512            // power of 2, load factor 200/512
#define HASH_MASK (HASH_SZ - 1)

__global__ void __launch_bounds__(TPB, 1)
prtnn_kernel(const int* __restrict__ x,
             const float* __restrict__ W,
             const float* __restrict__ bias,
             float* __restrict__ out)
{
    const int b = blockIdx.x;
    const int t = threadIdx.x;

    __shared__ int   table[HASH_SZ];
    __shared__ float warp_acc[TPB / 32][OUT];

    // init hash table (2 slots per thread) — overlaps with the x load below
    table[t]       = -1;
    table[t + TPB] = -1;

    // load this thread's hit indices (independent of table init)
    int f = -1;
    if (t < NHITS) {
        const int* xp = x + ((size_t)b * NHITS + t) * 3;
        f = xp[1] * D1 + xp[2];      // feature = i0*350 + i1
    }
    __syncthreads();

    float acc[OUT] = {0.f, 0.f, 0.f, 0.f, 0.f};
    if (t < NHITS) {
        // Speculatively issue the W-row gather NOW (idempotent), so the
        // ~577-cycle DRAM latency overlaps with the hash-based dedup.
        const float* w = W + (size_t)f * OUT;
        float wv[OUT];
        #pragma unroll
        for (int o = 0; o < OUT; ++o) wv[o] = __ldg(w + o);

        // hash-set insert: winner of the CAS for feature f is "unique"
        bool uniq = false;
        int slot = (f * 0x9E3779B1u) >> 23;   // top bits -> [0, 512)
        slot &= HASH_MASK;
        while (true) {
            int prev = atomicCAS(&table[slot], -1, f);
            if (prev == -1) { uniq = true;  break; }   // inserted: first occurrence
            if (prev == f)  { uniq = false; break; }   // already present: duplicate
            slot = (slot + 1) & HASH_MASK;             // linear probe
        }

        const float m = uniq ? 1.0f : 0.0f;
        #pragma unroll
        for (int o = 0; o < OUT; ++o) acc[o] = wv[o] * m;
    }

    // warp tree-reduce the 5 partial sums
    #pragma unroll
    for (int off = 16; off > 0; off >>= 1) {
        #pragma unroll
        for (int o = 0; o < OUT; ++o)
            acc[o] += __shfl_down_sync(0xFFFFFFFFu, acc[o], off);
    }
    const int wid  = t >> 5;
    const int lane = t & 31;
    if (lane == 0) {
        #pragma unroll
        for (int o = 0; o < OUT; ++o) warp_acc[wid][o] = acc[o];
    }
    __syncthreads();

    // cross-warp reduce + bias + store
    if (t < OUT) {
        float s = bias[t];
        #pragma unroll
        for (int w = 0; w < TPB / 32; ++w) s += warp_acc[w][t];
        out[(size_t)b * OUT + t] = s;
    }
}

extern "C" void kernel_launch(void* const* d_in, const int* in_sizes, int n_in,
                              void* d_out, int out_size)
{
    const int*   x    = (const int*)d_in[0];
    const float* W    = (const float*)d_in[1];
    const float* bias = (const float*)d_in[2];
    float*       out  = (float*)d_out;

    prtnn_kernel<<<NB, TPB>>>(x, W, bias, out);
}

// round 4
// speedup vs baseline: 1.6857x; 1.1714x over previous
#include <cuda_runtime.h>
#include <cuda_bf16.h>
#include <cstdint>

// out[b, o] = bias[o] + sum over UNIQUE (i0,i1) pairs in batch row b of
//             W[i0*350 + i1, o]
//
// Inputs (metadata order):
//   d_in[0]: x    int32  [32, 200, 3]   (b, i0, i1)
//   d_in[1]: W    float  [2150400, 5]
//   d_in[2]: b    float  [5]
// Output: float [32, 5]

#define NB      32
#define NHITS   200
#define D1      350
#define OUT     5
#define TPB     224            // 7 warps: covers 200 hits, no dead 8th warp
#define HASH_SZ 512
#define HASH_MASK (HASH_SZ - 1)

__global__ void __launch_bounds__(TPB, 1)
prtnn_kernel(const int* __restrict__ x,
             const float* __restrict__ W,
             const float* __restrict__ bias,
             float* __restrict__ out)
{
    const int b = blockIdx.x;
    const int t = threadIdx.x;

    __shared__ int table[HASH_SZ];

    // Issue the x load FIRST so its latency overlaps table init + barrier.
    int f = -1;
    if (t < NHITS) {
        const int* xp = x + ((size_t)b * NHITS + t) * 3;
        f = __ldg(xp + 1) * D1 + __ldg(xp + 2);   // feature = i0*350 + i1
    }

    // hash-table init (stride loop, 2-3 slots/thread)
    #pragma unroll
    for (int s = t; s < HASH_SZ; s += TPB) table[s] = -1;

    // initialize this block's 5 outputs with the bias (ordered before the
    // epilogue atomics by the __syncthreads cta-scope fence)
    if (t < OUT) out[b * OUT + t] = __ldg(bias + t);

    __syncthreads();

    float acc[OUT] = {0.f, 0.f, 0.f, 0.f, 0.f};
    if (t < NHITS) {
        // Speculatively issue the W-row gather NOW (idempotent) so its memory
        // latency overlaps with the hash-based dedup below.
        const float* w = W + f * OUT;             // f*5 < 10.75M, fits int32
        float wv[OUT];
        #pragma unroll
        for (int o = 0; o < OUT; ++o) wv[o] = __ldg(w + o);

        // hash-set insert: winner of the CAS for feature f is "unique".
        // First probe is straight-line (hits ~95%+); collisions re-probe.
        unsigned slot = ((unsigned)f * 0x9E3779B1u >> 23) & HASH_MASK;
        int prev = atomicCAS(&table[slot], -1, f);
        while (prev != -1 && prev != f) {
            slot = (slot + 1) & HASH_MASK;
            prev = atomicCAS(&table[slot], -1, f);
        }
        const float m = (prev == -1) ? 1.0f : 0.0f;   // first occurrence only
        #pragma unroll
        for (int o = 0; o < OUT; ++o) acc[o] = wv[o] * m;
    }

    // warp tree-reduce the 5 partial sums
    #pragma unroll
    for (int off = 16; off > 0; off >>= 1) {
        #pragma unroll
        for (int o = 0; o < OUT; ++o)
            acc[o] += __shfl_down_sync(0xFFFFFFFFu, acc[o], off);
    }

    // lane 0 of each warp accumulates directly into global out
    // (REDG no-return; out was bias-initialized before the barrier)
    if ((t & 31) == 0) {
        #pragma unroll
        for (int o = 0; o < OUT; ++o)
            atomicAdd(&out[b * OUT + o], acc[o]);
    }
}

extern "C" void kernel_launch(void* const* d_in, const int* in_sizes, int n_in,
                              void* d_out, int out_size)
{
    const int*   x    = (const int*)d_in[0];
    const float* W    = (const float*)d_in[1];
    const float* bias = (const float*)d_in[2];
    float*       out  = (float*)d_out;

    prtnn_kernel<<<NB, TPB>>>(x, W, bias, out);
}